// round 5
// baseline (speedup 1.0000x reference)
#include <cuda_runtime.h>
#include <math.h>

#define H_ 256
#define B_ 256
#define T_ 512
#define D_ 32
#define HOR_ 24
#define NQ_ 3
#define BH_ (B_*H_)
#define NBLK 128
#define SVS 36      // v-tile row stride (floats): 16B-aligned rows, conflict-free at 8B grain

// ---------------- device scratch ----------------
__device__ float g_zero[BH_];              // never written: initial h/c = 0
__device__ float g_h1[T_][BH_];            // layer0 outputs per t
__device__ float g_enc[T_][BH_];           // layer1 outputs per t
__device__ float g_energy[B_*T_];
__device__ float g_ctx[BH_];
__device__ float g_dh0[HOR_][BH_];
__device__ float g_dh1[HOR_][BH_];
__device__ volatile unsigned g_gen;
__device__ unsigned g_count;

// ---------------- helpers ----------------
static __device__ __forceinline__ unsigned long long fma2_(unsigned long long a,
                                                           unsigned long long b,
                                                           unsigned long long c) {
    unsigned long long d;
    asm("fma.rn.f32x2 %0, %1, %2, %3;" : "=l"(d) : "l"(a), "l"(b), "l"(c));
    return d;
}
static __device__ __forceinline__ float hsum2_(unsigned long long a) {
    float lo, hi;
    asm("mov.b64 {%0, %1}, %2;" : "=f"(lo), "=f"(hi) : "l"(a));
    return lo + hi;
}
static __device__ __forceinline__ float sigm_(float x) { return 1.0f / (1.0f + expf(-x)); }

// software grid barrier: all NBLK blocks co-resident (1 block/SM)
static __device__ __forceinline__ void grid_sync() {
    __syncthreads();
    if (threadIdx.x == 0) {
        __threadfence();
        unsigned gen = g_gen;
        if (atomicAdd(&g_count, 1u) == NBLK - 1) {
            g_count = 0;
            __threadfence();
            g_gen = gen + 1;
        } else {
            while (g_gen == gen) { }
        }
    }
    __syncthreads();
}

// ---------------- gate GEMM: 32 gate-rows x 64 batch, K split across warp-halves ----------
// 256 threads. half = tid>>7 owns K-chunks [half*nch, (half+1)*nch). Within half:
// thread (jq,bq) computes rows jq*4+i, cols bq+16*j, f32x2 pairs along k.
// W resident in smem (strides are multiples of 4 floats -> LDS.128 legal).
static __device__ __forceinline__ void gates_compute(
    const float* __restrict__ sW, int sws,
    float* __restrict__ sV, float* __restrict__ sG, const float* __restrict__ sB,
    const float* __restrict__ in1, long long in1_str, int K1,
    const float* __restrict__ hprev, int nchunks,
    int tid, int bbase)
{
    const int half = tid >> 7;
    const int tid7 = tid & 127;
    const int jq = tid7 >> 4;
    const int bq = tid7 & 15;
    const int nch = nchunks >> 1;
    const int cbase = half * nch;
    float* myV = sV + half * (2 * 64 * SVS);

    unsigned long long acc[16];
    #pragma unroll
    for (int i = 0; i < 16; i++) acc[i] = 0ull;

    const int s_row = tid7 >> 2;     // 0..31 (x2 rounds = 64 rows)
    const int s_kq  = tid7 & 3;

    float4 pre[2];
    #pragma unroll
    for (int r = 0; r < 2; r++) {
        int row = s_row + r * 32;
        int k = cbase * 16 + s_kq * 4;
        const float* src = (k < K1) ? (in1 + (size_t)(bbase + row) * in1_str + k)
                                    : (hprev + (size_t)(bbase + row) * H_ + (k - K1));
        pre[r] = *(const float4*)src;
    }

    for (int ci = 0; ci < nch; ci++) {
        float* buf = myV + (ci & 1) * (64 * SVS);
        #pragma unroll
        for (int r = 0; r < 2; r++)
            *(float4*)&buf[(s_row + r * 32) * SVS + s_kq * 4] = pre[r];
        __syncthreads();
        if (ci + 1 < nch) {
            #pragma unroll
            for (int r = 0; r < 2; r++) {
                int row = s_row + r * 32;
                int k = (cbase + ci + 1) * 16 + s_kq * 4;
                const float* src = (k < K1) ? (in1 + (size_t)(bbase + row) * in1_str + k)
                                            : (hprev + (size_t)(bbase + row) * H_ + (k - K1));
                pre[r] = *(const float4*)src;
            }
        }
        const float* wp = sW + (cbase + ci) * 16;
        #pragma unroll
        for (int k4 = 0; k4 < 4; k4++) {
            ulonglong2 wv[4], vv[4];
            #pragma unroll
            for (int i = 0; i < 4; i++)
                wv[i] = *(const ulonglong2*)(wp + (jq * 4 + i) * sws + k4 * 4);
            #pragma unroll
            for (int j = 0; j < 4; j++)
                vv[j] = *(const ulonglong2*)(buf + (bq + 16 * j) * SVS + k4 * 4);
            #pragma unroll
            for (int i = 0; i < 4; i++)
                #pragma unroll
                for (int j = 0; j < 4; j++) {
                    acc[i * 4 + j] = fma2_(wv[i].x, vv[j].x, acc[i * 4 + j]);
                    acc[i * 4 + j] = fma2_(wv[i].y, vv[j].y, acc[i * 4 + j]);
                }
        }
    }
    // merge halves into sG (row stride 66)
    if (half == 0) {
        #pragma unroll
        for (int i = 0; i < 4; i++) {
            int j = jq * 4 + i;
            float bv = sB[j];
            #pragma unroll
            for (int jj = 0; jj < 4; jj++)
                sG[j * 66 + bq + 16 * jj] = hsum2_(acc[i * 4 + jj]) + bv;
        }
    }
    __syncthreads();
    if (half == 1) {
        #pragma unroll
        for (int i = 0; i < 4; i++) {
            int j = jq * 4 + i;
            #pragma unroll
            for (int jj = 0; jj < 4; jj++)
                sG[j * 66 + bq + 16 * jj] += hsum2_(acc[i * 4 + jj]);
        }
    }
    // caller must __syncthreads() (or grid_sync) before reading sG
}

// activation + state update with 256 threads (2 cells each); c kept in registers
static __device__ __forceinline__ void lstm_activate(
    const float* __restrict__ sG, float* crr, float* __restrict__ hout,
    int tid, int hbase, int bbase,
    const float* __restrict__ cinit,
    const float* __restrict__ sWih0, const float* __restrict__ sDin)
{
    #pragma unroll
    for (int r = 0; r < 2; r++) {
        int cell = tid + r * 256;
        int b = cell >> 3, hh = cell & 7;
        float gi = sG[hh * 66 + b];
        float gf = sG[(8 + hh) * 66 + b];
        float gg = sG[(16 + hh) * 66 + b];
        float go = sG[(24 + hh) * 66 + b];
        if (sWih0) {
            float di = sDin[b];
            gi += sWih0[hh] * di;
            gf += sWih0[8 + hh] * di;
            gg += sWih0[16 + hh] * di;
            go += sWih0[24 + hh] * di;
        }
        float c = cinit ? cinit[(size_t)(bbase + b) * H_ + hbase + hh] : crr[r];
        float cn = sigm_(gf) * c + sigm_(gi) * tanhf(gg);
        crr[r] = cn;
        hout[(size_t)(bbase + b) * H_ + hbase + hh] = sigm_(go) * tanhf(cn);
    }
}

// ---------------- persistent encoder ----------------
#define SW0S 292
#define SW1S 516
__global__ void __launch_bounds__(256) enc_kernel(
    const float* __restrict__ x,
    const float* __restrict__ Wih0, const float* __restrict__ Whh0, const float* __restrict__ b0,
    const float* __restrict__ Wih1, const float* __restrict__ Whh1, const float* __restrict__ b1)
{
    extern __shared__ float smem[];
    float* sW0 = smem;                     // 32*SW0S
    float* sW1 = sW0 + 32 * SW0S;          // 32*SW1S
    float* sV  = sW1 + 32 * SW1S;          // 4*64*SVS (2 halves x 2 bufs)
    float* sG  = sV + 4 * 64 * SVS;        // 32*66
    float* sB0 = sG + 32 * 66;             // 32
    float* sB1 = sB0 + 32;                 // 32

    const int tid = threadIdx.x;
    const int hbase = (blockIdx.x & 31) * 8;
    const int bbase = (blockIdx.x >> 5) * 64;

    for (int idx = tid; idx < 32 * 144; idx += 256) {
        int j = idx / 144, p = idx % 144;
        int grow = (j >> 3) * H_ + hbase + (j & 7);
        const float* src = (p < 16) ? (Wih0 + (size_t)grow * D_ + 2 * p)
                                    : (Whh0 + (size_t)grow * H_ + 2 * (p - 16));
        *(float2*)&sW0[j * SW0S + 2 * p] = *(const float2*)src;
    }
    for (int idx = tid; idx < 32 * 256; idx += 256) {
        int j = idx >> 8, p = idx & 255;
        int grow = (j >> 3) * H_ + hbase + (j & 7);
        const float* src = (p < 128) ? (Wih1 + (size_t)grow * H_ + 2 * p)
                                     : (Whh1 + (size_t)grow * H_ + 2 * (p - 128));
        *(float2*)&sW1[j * SW1S + 2 * p] = *(const float2*)src;
    }
    if (tid < 32) {
        int grow = (tid >> 3) * H_ + hbase + (tid & 7);
        sB0[tid] = b0[grow];
        sB1[tid] = b1[grow];
    }
    __syncthreads();

    float c0r[2] = {0.f, 0.f};
    float c1r[2] = {0.f, 0.f};

    for (int t = 0; t < T_; t++) {
        const float* hp0 = t ? g_h1[t - 1] : g_zero;
        gates_compute(sW0, SW0S, sV, sG, sB0,
                      x + (size_t)t * D_, (long long)(T_ * D_), D_, hp0, 18, tid, bbase);
        __syncthreads();
        lstm_activate(sG, c0r, g_h1[t], tid, hbase, bbase, nullptr, nullptr, nullptr);
        grid_sync();   // orders h1[t] (for gates1) and enc[t-1] (from prev iter)

        const float* hp1 = t ? g_enc[t - 1] : g_zero;
        gates_compute(sW1, SW1S, sV, sG, sB1,
                      g_h1[t], (long long)H_, H_, hp1, 32, tid, bbase);
        __syncthreads();
        lstm_activate(sG, c1r, g_enc[t], tid, hbase, bbase, nullptr, nullptr, nullptr);
        // no sync: layer0 of t+1 depends only on h1[t], ordered at next grid_sync
    }
}

// ---------------- attention energy: warp per (b,t) ----------------
__global__ void __launch_bounds__(128) energy_kernel(
    const float* __restrict__ aW, const float* __restrict__ aV)
{
    __shared__ float sRow[4][256];
    int w = threadIdx.x >> 5, lane = threadIdx.x & 31;
    int bt = blockIdx.x * 4 + w;
    int b = bt >> 9, t = bt & 511;
    const float* row = g_enc[t] + (size_t)b * H_;
    #pragma unroll
    for (int r = 0; r < 2; r++)
        reinterpret_cast<float4*>(sRow[w])[lane + r * 32] =
            reinterpret_cast<const float4*>(row)[lane + r * 32];
    __syncwarp();
    float a0 = 0.f, a1 = 0.f, a2 = 0.f, a3 = 0.f;
    #pragma unroll 4
    for (int h = 0; h < H_; h++) {
        float e = sRow[w][h];
        float4 wv = reinterpret_cast<const float4*>(aW)[h * 32 + lane];
        a0 += e * wv.x; a1 += e * wv.y; a2 += e * wv.z; a3 += e * wv.w;
    }
    float s = tanhf(a0) * aV[lane * 4 + 0] + tanhf(a1) * aV[lane * 4 + 1]
            + tanhf(a2) * aV[lane * 4 + 2] + tanhf(a3) * aV[lane * 4 + 3];
    #pragma unroll
    for (int off = 16; off; off >>= 1) s += __shfl_xor_sync(0xffffffffu, s, off);
    if (lane == 0) g_energy[(size_t)b * T_ + t] = s;
}

// ---------------- softmax over t + context: block per b ----------------
__global__ void __launch_bounds__(256) softmax_ctx_kernel()
{
    __shared__ float sw[512];
    __shared__ float sred[9];
    int b = blockIdx.x, tid = threadIdx.x;
    float e0 = g_energy[(size_t)b * T_ + tid];
    float e1 = g_energy[(size_t)b * T_ + 256 + tid];
    float m = fmaxf(e0, e1);
    #pragma unroll
    for (int off = 16; off; off >>= 1) m = fmaxf(m, __shfl_xor_sync(0xffffffffu, m, off));
    if ((tid & 31) == 0) sred[tid >> 5] = m;
    __syncthreads();
    if (tid == 0) { float M = sred[0]; for (int i = 1; i < 8; i++) M = fmaxf(M, sred[i]); sred[8] = M; }
    __syncthreads();
    float M = sred[8];
    float p0 = expf(e0 - M), p1 = expf(e1 - M);
    float s = p0 + p1;
    #pragma unroll
    for (int off = 16; off; off >>= 1) s += __shfl_xor_sync(0xffffffffu, s, off);
    __syncthreads();
    if ((tid & 31) == 0) sred[tid >> 5] = s;
    __syncthreads();
    if (tid == 0) { float S = 0.f; for (int i = 0; i < 8; i++) S += sred[i]; sred[8] = 1.f / S; }
    __syncthreads();
    float inv = sred[8];
    sw[tid] = p0 * inv;
    sw[256 + tid] = p1 * inv;
    __syncthreads();
    float acc = 0.f;
    #pragma unroll 4
    for (int t = 0; t < T_; t++) acc += sw[t] * g_enc[t][(size_t)b * H_ + tid];
    g_ctx[(size_t)b * H_ + tid] = acc;
}

// ---------------- persistent decoder ----------------
#define SD0S 260
__global__ void __launch_bounds__(256) dec_kernel(
    const float* __restrict__ x,
    const float* __restrict__ dWih0, const float* __restrict__ dWhh0, const float* __restrict__ db0,
    const float* __restrict__ dWih1, const float* __restrict__ dWhh1, const float* __restrict__ db1)
{
    extern __shared__ float smem[];
    float* sWd0  = smem;                    // 32*SD0S (Whh0 slice)
    float* sWd1  = sWd0 + 32 * SD0S;        // 32*SW1S (Wih1|Whh1 slice)
    float* sV    = sWd1 + 32 * SW1S;        // 4*64*SVS
    float* sG    = sV + 4 * 64 * SVS;       // 32*66
    float* sWih0 = sG + 32 * 66;            // 32
    float* sBd0  = sWih0 + 32;              // 32
    float* sBd1  = sBd0 + 32;               // 32
    float* sDin  = sBd1 + 32;               // 64

    const int tid = threadIdx.x;
    const int hbase = (blockIdx.x & 31) * 8;
    const int bbase = (blockIdx.x >> 5) * 64;

    for (int idx = tid; idx < 32 * 128; idx += 256) {
        int j = idx >> 7, p = idx & 127;
        int grow = (j >> 3) * H_ + hbase + (j & 7);
        *(float2*)&sWd0[j * SD0S + 2 * p] =
            *(const float2*)(dWhh0 + (size_t)grow * H_ + 2 * p);
    }
    for (int idx = tid; idx < 32 * 256; idx += 256) {
        int j = idx >> 8, p = idx & 255;
        int grow = (j >> 3) * H_ + hbase + (j & 7);
        const float* src = (p < 128) ? (dWih1 + (size_t)grow * H_ + 2 * p)
                                     : (dWhh1 + (size_t)grow * H_ + 2 * (p - 128));
        *(float2*)&sWd1[j * SW1S + 2 * p] = *(const float2*)src;
    }
    if (tid < 32) {
        int grow = (tid >> 3) * H_ + hbase + (tid & 7);
        sWih0[tid] = dWih0[grow];
        sBd0[tid]  = db0[grow];
        sBd1[tid]  = db1[grow];
    }
    __syncthreads();

    float cd0[2], cd1[2];
    for (int s = 0; s < HOR_; s++) {
        const float* hp0 = s ? g_dh0[s - 1] : g_ctx;
        gates_compute(sWd0, SD0S, sV, sG, sBd0,
                      g_zero, (long long)H_, 0, hp0, 16, tid, bbase);
        grid_sync();   // orders dh1[s-1] (for sDin) + finalizes sG
        if (tid < 64) {
            sDin[tid] = (s == 0)
                ? x[((size_t)(bbase + tid) * T_ + (T_ - 1)) * D_ + (D_ - 1)]
                : g_dh1[s - 1][(size_t)(bbase + tid) * H_];
        }
        __syncthreads();
        lstm_activate(sG, cd0, g_dh0[s], tid, hbase, bbase,
                      (s == 0) ? g_ctx : nullptr, sWih0, sDin);
        grid_sync();   // orders dh0[s] before gates1

        const float* hp1 = s ? g_dh1[s - 1] : g_ctx;
        gates_compute(sWd1, SW1S, sV, sG, sBd1,
                      g_dh0[s], (long long)H_, H_, hp1, 32, tid, bbase);
        __syncthreads();
        lstm_activate(sG, cd1, g_dh1[s], tid, hbase, bbase,
                      (s == 0) ? g_ctx : nullptr, nullptr, nullptr);
    }
}

// ---------------- final projection: block per b ----------------
__global__ void __launch_bounds__(128) pred_kernel(
    const float* __restrict__ qW, const float* __restrict__ qb, float* __restrict__ out)
{
    __shared__ float sL[256];
    int b = blockIdx.x, tid = threadIdx.x;
    const float* last = g_dh1[HOR_ - 1];
    sL[tid] = last[(size_t)b * H_ + tid];
    sL[tid + 128] = last[(size_t)b * H_ + tid + 128];
    __syncthreads();
    if (tid < NQ_ * HOR_) {
        const float* wr = qW + (size_t)tid * H_;
        float acc = 0.f;
        #pragma unroll 8
        for (int h = 0; h < H_; h++) acc += sL[h] * wr[h];
        out[(size_t)b * (NQ_ * HOR_) + tid] = acc + qb[tid];
    }
}

// ---------------- launch ----------------
extern "C" void kernel_launch(void* const* d_in, const int* in_sizes, int n_in,
                              void* d_out, int out_size)
{
    const float* x      = (const float*)d_in[0];
    const float* e_Wih0 = (const float*)d_in[1];
    const float* e_Whh0 = (const float*)d_in[2];
    const float* e_b0   = (const float*)d_in[3];
    const float* e_Wih1 = (const float*)d_in[4];
    const float* e_Whh1 = (const float*)d_in[5];
    const float* e_b1   = (const float*)d_in[6];
    const float* d_Wih0 = (const float*)d_in[7];
    const float* d_Whh0 = (const float*)d_in[8];
    const float* d_b0   = (const float*)d_in[9];
    const float* d_Wih1 = (const float*)d_in[10];
    const float* d_Whh1 = (const float*)d_in[11];
    const float* d_b1   = (const float*)d_in[12];
    const float* aW     = (const float*)d_in[13];
    const float* aV     = (const float*)d_in[14];
    const float* qW     = (const float*)d_in[15];
    const float* qb     = (const float*)d_in[16];

    const int ENC_SMEM = (32 * SW0S + 32 * SW1S + 4 * 64 * SVS + 32 * 66 + 64) * 4;
    const int DEC_SMEM = (32 * SD0S + 32 * SW1S + 4 * 64 * SVS + 32 * 66 + 160) * 4;
    cudaFuncSetAttribute(enc_kernel, cudaFuncAttributeMaxDynamicSharedMemorySize, ENC_SMEM);
    cudaFuncSetAttribute(dec_kernel, cudaFuncAttributeMaxDynamicSharedMemorySize, DEC_SMEM);

    enc_kernel<<<NBLK, 256, ENC_SMEM>>>(x, e_Wih0, e_Whh0, e_b0, e_Wih1, e_Whh1, e_b1);
    energy_kernel<<<B_ * T_ / 4, 128>>>(aW, aV);
    softmax_ctx_kernel<<<B_, 256>>>();
    dec_kernel<<<NBLK, 256, DEC_SMEM>>>(x, d_Wih0, d_Whh0, d_b0, d_Wih1, d_Whh1, d_b1);
    pred_kernel<<<B_, 128>>>(qW, qb, (float*)d_out);
}

// round 7
// speedup vs baseline: 1.8218x; 1.8218x over previous
#include <cuda_runtime.h>
#include <cuda_bf16.h>
#include <math.h>

#define H_ 256
#define B_ 256
#define T_ 512
#define D_ 32
#define HOR_ 24
#define NQ_ 3
#define BH_ (B_*H_)
#define NBLK 128
#define KT1_ 32
#define KT0_ 18
#define KTD_ 16

__device__ float    g_zero[BH_];
__device__ unsigned g_zerob[BH_];
__device__ float    g_h1[T_][BH_];
__device__ float    g_enc[T_][BH_];
__device__ unsigned g_h1b[T_][BH_];
__device__ unsigned g_encb[T_][BH_];
__device__ unsigned g_xb[B_*T_*D_];
__device__ float    g_energy[B_*T_];
__device__ float    g_ctx[BH_];
__device__ unsigned g_ctxb[BH_];
__device__ float    g_dh0[HOR_][BH_];
__device__ float    g_dh1[HOR_][BH_];
__device__ unsigned g_dh0b[HOR_][BH_];
__device__ unsigned g_dh1b[HOR_][BH_];
__device__ volatile unsigned g_gen;
__device__ unsigned g_count;

static __device__ __forceinline__ float sigm_(float x) { return 1.0f / (1.0f + expf(-x)); }

static __device__ __forceinline__ unsigned pack_hl(float v) {
    __nv_bfloat16 h = __float2bfloat16(v);
    __nv_bfloat16 l = __float2bfloat16(v - __bfloat162float(h));
    return (unsigned)__bfloat16_as_ushort(h) | ((unsigned)__bfloat16_as_ushort(l) << 16);
}
static __device__ __forceinline__ void mma_bf16(float* d, const uint4& a, unsigned b0, unsigned b1) {
    asm volatile("mma.sync.aligned.m16n8k16.row.col.f32.bf16.bf16.f32 "
                 "{%0,%1,%2,%3}, {%4,%5,%6,%7}, {%8,%9}, {%0,%1,%2,%3};"
                 : "+f"(d[0]), "+f"(d[1]), "+f"(d[2]), "+f"(d[3])
                 : "r"(a.x), "r"(a.y), "r"(a.z), "r"(a.w), "r"(b0), "r"(b1));
}
static __device__ __forceinline__ void ldm2(unsigned& r0, unsigned& r1, const void* p) {
    unsigned a = (unsigned)__cvta_generic_to_shared(p);
    asm volatile("ldmatrix.sync.aligned.m8n8.x2.shared.b16 {%0,%1}, [%2];"
                 : "=r"(r0), "=r"(r1) : "r"(a));
}
static __device__ __forceinline__ void grid_sync() {
    __syncthreads();
    if (threadIdx.x == 0) {
        __threadfence();
        unsigned gen = g_gen;
        if (atomicAdd(&g_count, 1u) == NBLK - 1) {
            g_count = 0; __threadfence(); g_gen = gen + 1;
        } else { while (g_gen == gen) { } }
    }
    __syncthreads();
}

// pack W slice into A-fragment layout (hi/lo), once per kernel.
// Fragment region size: 2(mt) * nKT * 32 lanes * 16B = 1024*nKT bytes.
static __device__ void init_afrag(unsigned short* Ah, unsigned short* Al,
                                  const float* Wih, int wih_cols,
                                  const float* Whh, int K, int nKT, int tid, int hbase)
{
    for (int idx = tid; idx < 32 * K; idx += 256) {
        int j = idx / K, k = idx - j * K;
        int grow = (j >> 3) * H_ + hbase + (j & 7);
        float wv = (k < wih_cols) ? Wih[(size_t)grow * wih_cols + k]
                                  : Whh[(size_t)grow * H_ + (k - wih_cols)];
        int m = j & 15, kt = k >> 4, kk = k & 15;
        int reg = (m >> 3) | ((kk >> 3) << 1);
        int lane = (m & 7) * 4 + ((kk & 7) >> 1);
        int off = (((j >> 4) * nKT + kt) * 32 + lane) * 8 + reg * 2 + (kk & 1);
        __nv_bfloat16 h = __float2bfloat16(wv);
        Ah[off] = __bfloat16_as_ushort(h);
        Al[off] = __bfloat16_as_ushort(__float2bfloat16(wv - __bfloat162float(h)));
    }
}

// gate GEMM: 32 gate-rows x 64 batch via mma. caller syncs before reading sG.
static __device__ __forceinline__ void gates_mma(
    const uint4* __restrict__ Ahi, const uint4* __restrict__ Alo, int nKT,
    const unsigned* __restrict__ in1b, int in1_str, int K1,
    const unsigned* __restrict__ hprevb,
    char* stgh, char* stgl, float* sG, const float* sB, int tid, int bbase)
{
    const int n_st = tid >> 2, kq = tid & 3;
    const int w = tid >> 5, lane = tid & 31;
    const int mt = w & 1, nw = w >> 1;
    const int brow = lane & 7, bkh = (lane >> 3) & 1;
    float acc0[4] = {0,0,0,0}, acc1[4] = {0,0,0,0};
    const int nchunks = (nKT + 3) >> 2;

    uint4 pre[4];
    int nkt0 = nKT < 4 ? nKT : 4;
    for (int i = 0; i < nkt0; i++) {
        int kg = kq * 4 + i * 16;
        const unsigned* src = (kg < K1) ? in1b + (size_t)(bbase + n_st) * in1_str + kg
                                        : hprevb + (size_t)(bbase + n_st) * H_ + (kg - K1);
        pre[i] = *(const uint4*)src;
    }
    for (int c = 0; c < nchunks; c++) {
        int cb = c * 4, nkt = nKT - cb; if (nkt > 4) nkt = 4;
        char* bh = stgh + (c & 1) * 9216;
        char* bl = stgl + (c & 1) * 9216;
        for (int i = 0; i < nkt; i++) {
            unsigned hiA = __byte_perm(pre[i].x, pre[i].y, 0x5410);
            unsigned loA = __byte_perm(pre[i].x, pre[i].y, 0x7632);
            unsigned hiB = __byte_perm(pre[i].z, pre[i].w, 0x5410);
            unsigned loB = __byte_perm(pre[i].z, pre[i].w, 0x7632);
            int koff = (kq * 4 + i * 16) * 2;
            *(unsigned long long*)(bh + n_st * 144 + koff) =
                (unsigned long long)hiA | ((unsigned long long)hiB << 32);
            *(unsigned long long*)(bl + n_st * 144 + koff) =
                (unsigned long long)loA | ((unsigned long long)loB << 32);
        }
        __syncthreads();
        if (c + 1 < nchunks) {
            int cb2 = cb + 4, nktn = nKT - cb2; if (nktn > 4) nktn = 4;
            for (int i = 0; i < nktn; i++) {
                int kg = cb2 * 16 + kq * 4 + i * 16;
                const unsigned* src = (kg < K1) ? in1b + (size_t)(bbase + n_st) * in1_str + kg
                                                : hprevb + (size_t)(bbase + n_st) * H_ + (kg - K1);
                pre[i] = *(const uint4*)src;
            }
        }
        for (int lt = 0; lt < nkt; lt++) {
            uint4 ah = Ahi[(mt * nKT + cb + lt) * 32 + lane];
            uint4 al = Alo[(mt * nKT + cb + lt) * 32 + lane];
            #pragma unroll
            for (int nf = 0; nf < 2; nf++) {
                int n8 = nw * 2 + nf;
                const char* ph = bh + (n8 * 8 + brow) * 144 + lt * 32 + bkh * 16;
                const char* pl = bl + (n8 * 8 + brow) * 144 + lt * 32 + bkh * 16;
                unsigned b0, b1, c0, c1;
                ldm2(b0, b1, ph);
                ldm2(c0, c1, pl);
                float* acc = nf ? acc1 : acc0;
                mma_bf16(acc, ah, b0, b1);
                mma_bf16(acc, al, b0, b1);
                mma_bf16(acc, ah, c0, c1);
            }
        }
    }
    int g = lane >> 2, tg = lane & 3;
    int row0 = mt * 16 + g, row1 = row0 + 8;
    float bv0 = sB[row0], bv1 = sB[row1];
    #pragma unroll
    for (int nf = 0; nf < 2; nf++) {
        float* acc = nf ? acc1 : acc0;
        int cc = (nw * 2 + nf) * 8 + tg * 2;
        sG[row0 * 66 + cc]     = acc[0] + bv0;
        sG[row0 * 66 + cc + 1] = acc[1] + bv0;
        sG[row1 * 66 + cc]     = acc[2] + bv1;
        sG[row1 * 66 + cc + 1] = acc[3] + bv1;
    }
}

static __device__ __forceinline__ void lstm_activate(
    const float* __restrict__ sG, float* crr,
    float* __restrict__ hout, unsigned* __restrict__ houtb,
    int tid, int hbase, int bbase, const float* __restrict__ cinit,
    const float* __restrict__ sWih0, const float* __restrict__ sDin)
{
    #pragma unroll
    for (int r = 0; r < 2; r++) {
        int cell = tid + r * 256;
        int b = cell >> 3, hh = cell & 7;
        float gi = sG[hh * 66 + b], gf = sG[(8 + hh) * 66 + b];
        float gg = sG[(16 + hh) * 66 + b], go = sG[(24 + hh) * 66 + b];
        if (sWih0) {
            float di = sDin[b];
            gi += sWih0[hh] * di; gf += sWih0[8 + hh] * di;
            gg += sWih0[16 + hh] * di; go += sWih0[24 + hh] * di;
        }
        size_t gidx = (size_t)(bbase + b) * H_ + hbase + hh;
        float c = cinit ? cinit[gidx] : crr[r];
        float cn = sigm_(gf) * c + sigm_(gi) * tanhf(gg);
        crr[r] = cn;
        float hn = sigm_(go) * tanhf(cn);
        hout[gidx] = hn;
        houtb[gidx] = pack_hl(hn);
    }
}

__global__ void pack_x_kernel(const float* __restrict__ x) {
    int i = blockIdx.x * blockDim.x + threadIdx.x;
    if (i < B_ * T_ * D_) g_xb[i] = pack_hl(x[i]);
}

// enc smem (bytes), CORRECT sizes (1024*nKT per A region):
// A1h 0..32768 | A1l 32768..65536 | A0h 65536..83968 | A0l 83968..102400
// stgh 102400..120832 | stgl 120832..139264 | sG 139264..147712 | sB0 147712 | sB1 147840
#define ENC_SMEM_ 147968
__global__ void __launch_bounds__(256) enc_kernel(
    const float* __restrict__ Wih0, const float* __restrict__ Whh0, const float* __restrict__ b0,
    const float* __restrict__ Wih1, const float* __restrict__ Whh1, const float* __restrict__ b1)
{
    extern __shared__ char sm[];
    uint4* A1h = (uint4*)sm;             uint4* A1l = (uint4*)(sm + 32768);
    uint4* A0h = (uint4*)(sm + 65536);   uint4* A0l = (uint4*)(sm + 83968);
    char* stgh = sm + 102400;            char* stgl = sm + 120832;
    float* sG  = (float*)(sm + 139264);
    float* sB0 = (float*)(sm + 147712);  float* sB1 = (float*)(sm + 147840);

    const int tid = threadIdx.x;
    const int hbase = (blockIdx.x & 31) * 8;
    const int bbase = (blockIdx.x >> 5) * 64;

    init_afrag((unsigned short*)A0h, (unsigned short*)A0l, Wih0, D_, Whh0, D_ + H_, KT0_, tid, hbase);
    init_afrag((unsigned short*)A1h, (unsigned short*)A1l, Wih1, H_, Whh1, 2 * H_, KT1_, tid, hbase);
    if (tid < 32) {
        int grow = (tid >> 3) * H_ + hbase + (tid & 7);
        sB0[tid] = b0[grow]; sB1[tid] = b1[grow];
    }
    __syncthreads();

    float c0r[2] = {0,0}, c1r[2] = {0,0};
    for (int t = 0; t < T_; t++) {
        gates_mma(A0h, A0l, KT0_, g_xb + (size_t)t * D_, T_ * D_, D_,
                  t ? g_h1b[t - 1] : g_zerob, stgh, stgl, sG, sB0, tid, bbase);
        __syncthreads();
        lstm_activate(sG, c0r, g_h1[t], g_h1b[t], tid, hbase, bbase, 0, 0, 0);
        grid_sync();
        gates_mma(A1h, A1l, KT1_, g_h1b[t], H_, H_,
                  t ? g_encb[t - 1] : g_zerob, stgh, stgl, sG, sB1, tid, bbase);
        __syncthreads();
        lstm_activate(sG, c1r, g_enc[t], g_encb[t], tid, hbase, bbase, 0, 0, 0);
    }
}

__global__ void __launch_bounds__(128) energy_kernel(
    const float* __restrict__ aW, const float* __restrict__ aV)
{
    __shared__ float sRow[4][256];
    int w = threadIdx.x >> 5, lane = threadIdx.x & 31;
    int bt = blockIdx.x * 4 + w;
    int b = bt >> 9, t = bt & 511;
    const float* row = g_enc[t] + (size_t)b * H_;
    #pragma unroll
    for (int r = 0; r < 2; r++)
        ((float4*)sRow[w])[lane + r * 32] = ((const float4*)row)[lane + r * 32];
    __syncwarp();
    float a0 = 0, a1 = 0, a2 = 0, a3 = 0;
    #pragma unroll 4
    for (int h = 0; h < H_; h++) {
        float e = sRow[w][h];
        float4 wv = ((const float4*)aW)[h * 32 + lane];
        a0 += e * wv.x; a1 += e * wv.y; a2 += e * wv.z; a3 += e * wv.w;
    }
    float s = tanhf(a0) * aV[lane * 4] + tanhf(a1) * aV[lane * 4 + 1]
            + tanhf(a2) * aV[lane * 4 + 2] + tanhf(a3) * aV[lane * 4 + 3];
    #pragma unroll
    for (int off = 16; off; off >>= 1) s += __shfl_xor_sync(0xffffffffu, s, off);
    if (lane == 0) g_energy[(size_t)b * T_ + t] = s;
}

__global__ void __launch_bounds__(256) softmax_ctx_kernel()
{
    __shared__ float sw[512];
    __shared__ float sred[9];
    int b = blockIdx.x, tid = threadIdx.x;
    float e0 = g_energy[(size_t)b * T_ + tid];
    float e1 = g_energy[(size_t)b * T_ + 256 + tid];
    float m = fmaxf(e0, e1);
    #pragma unroll
    for (int off = 16; off; off >>= 1) m = fmaxf(m, __shfl_xor_sync(0xffffffffu, m, off));
    if ((tid & 31) == 0) sred[tid >> 5] = m;
    __syncthreads();
    if (tid == 0) { float M = sred[0]; for (int i = 1; i < 8; i++) M = fmaxf(M, sred[i]); sred[8] = M; }
    __syncthreads();
    float M = sred[8];
    float p0 = expf(e0 - M), p1 = expf(e1 - M);
    float s = p0 + p1;
    #pragma unroll
    for (int off = 16; off; off >>= 1) s += __shfl_xor_sync(0xffffffffu, s, off);
    __syncthreads();
    if ((tid & 31) == 0) sred[tid >> 5] = s;
    __syncthreads();
    if (tid == 0) { float S = 0; for (int i = 0; i < 8; i++) S += sred[i]; sred[8] = 1.f / S; }
    __syncthreads();
    float inv = sred[8];
    sw[tid] = p0 * inv; sw[256 + tid] = p1 * inv;
    __syncthreads();
    float acc = 0;
    #pragma unroll 4
    for (int t = 0; t < T_; t++) acc += sw[t] * g_enc[t][(size_t)b * H_ + tid];
    g_ctx[(size_t)b * H_ + tid] = acc;
    g_ctxb[(size_t)b * H_ + tid] = pack_hl(acc);
}

// dec smem (bytes):
// A0h 0..16384 | A0l 16384..32768 | A1h 32768..65536 | A1l 65536..98304
// stgh 98304..116736 | stgl 116736..135168 | sG 135168..143616
// sWih0 143616 | sB0 143744 | sB1 143872 | sDin 144000..144256
#define DEC_SMEM_ 144256
__global__ void __launch_bounds__(256) dec_kernel(
    const float* __restrict__ x,
    const float* __restrict__ dWih0, const float* __restrict__ dWhh0, const float* __restrict__ db0,
    const float* __restrict__ dWih1, const float* __restrict__ dWhh1, const float* __restrict__ db1)
{
    extern __shared__ char sm[];
    uint4* A0h = (uint4*)sm;             uint4* A0l = (uint4*)(sm + 16384);
    uint4* A1h = (uint4*)(sm + 32768);   uint4* A1l = (uint4*)(sm + 65536);
    char* stgh = sm + 98304;             char* stgl = sm + 116736;
    float* sG    = (float*)(sm + 135168);
    float* sWih0 = (float*)(sm + 143616);
    float* sB0   = (float*)(sm + 143744);
    float* sB1   = (float*)(sm + 143872);
    float* sDin  = (float*)(sm + 144000);

    const int tid = threadIdx.x;
    const int hbase = (blockIdx.x & 31) * 8;
    const int bbase = (blockIdx.x >> 5) * 64;

    init_afrag((unsigned short*)A0h, (unsigned short*)A0l, dWhh0, 0, dWhh0, H_, KTD_, tid, hbase);
    init_afrag((unsigned short*)A1h, (unsigned short*)A1l, dWih1, H_, dWhh1, 2 * H_, KT1_, tid, hbase);
    if (tid < 32) {
        int grow = (tid >> 3) * H_ + hbase + (tid & 7);
        sWih0[tid] = dWih0[grow]; sB0[tid] = db0[grow]; sB1[tid] = db1[grow];
    }
    __syncthreads();

    float cd0[2], cd1[2];
    for (int s = 0; s < HOR_; s++) {
        gates_mma(A0h, A0l, KTD_, g_zerob, H_, 0,
                  s ? g_dh0b[s - 1] : g_ctxb, stgh, stgl, sG, sB0, tid, bbase);
        grid_sync();
        if (tid < 64) {
            sDin[tid] = (s == 0)
                ? x[((size_t)(bbase + tid) * T_ + (T_ - 1)) * D_ + (D_ - 1)]
                : g_dh1[s - 1][(size_t)(bbase + tid) * H_];
        }
        __syncthreads();
        lstm_activate(sG, cd0, g_dh0[s], g_dh0b[s], tid, hbase, bbase,
                      s == 0 ? g_ctx : 0, sWih0, sDin);
        grid_sync();
        gates_mma(A1h, A1l, KT1_, g_dh0b[s], H_, H_,
                  s ? g_dh1b[s - 1] : g_ctxb, stgh, stgl, sG, sB1, tid, bbase);
        __syncthreads();
        lstm_activate(sG, cd1, g_dh1[s], g_dh1b[s], tid, hbase, bbase,
                      s == 0 ? g_ctx : 0, 0, 0);
    }
}

__global__ void __launch_bounds__(128) pred_kernel(
    const float* __restrict__ qW, const float* __restrict__ qb, float* __restrict__ out)
{
    __shared__ float sL[256];
    int b = blockIdx.x, tid = threadIdx.x;
    const float* last = g_dh1[HOR_ - 1];
    sL[tid] = last[(size_t)b * H_ + tid];
    sL[tid + 128] = last[(size_t)b * H_ + tid + 128];
    __syncthreads();
    if (tid < NQ_ * HOR_) {
        const float* wr = qW + (size_t)tid * H_;
        float acc = 0;
        #pragma unroll 8
        for (int h = 0; h < H_; h++) acc += sL[h] * wr[h];
        out[(size_t)b * (NQ_ * HOR_) + tid] = acc + qb[tid];
    }
}

extern "C" void kernel_launch(void* const* d_in, const int* in_sizes, int n_in,
                              void* d_out, int out_size)
{
    const float* x      = (const float*)d_in[0];
    const float* e_Wih0 = (const float*)d_in[1];
    const float* e_Whh0 = (const float*)d_in[2];
    const float* e_b0   = (const float*)d_in[3];
    const float* e_Wih1 = (const float*)d_in[4];
    const float* e_Whh1 = (const float*)d_in[5];
    const float* e_b1   = (const float*)d_in[6];
    const float* d_Wih0 = (const float*)d_in[7];
    const float* d_Whh0 = (const float*)d_in[8];
    const float* d_b0   = (const float*)d_in[9];
    const float* d_Wih1 = (const float*)d_in[10];
    const float* d_Whh1 = (const float*)d_in[11];
    const float* d_b1   = (const float*)d_in[12];
    const float* aW     = (const float*)d_in[13];
    const float* aV     = (const float*)d_in[14];
    const float* qW     = (const float*)d_in[15];
    const float* qb     = (const float*)d_in[16];

    cudaFuncSetAttribute(enc_kernel, cudaFuncAttributeMaxDynamicSharedMemorySize, ENC_SMEM_);
    cudaFuncSetAttribute(dec_kernel, cudaFuncAttributeMaxDynamicSharedMemorySize, DEC_SMEM_);

    pack_x_kernel<<<(B_ * T_ * D_ + 255) / 256, 256>>>(x);
    enc_kernel<<<NBLK, 256, ENC_SMEM_>>>(e_Wih0, e_Whh0, e_b0, e_Wih1, e_Whh1, e_b1);
    energy_kernel<<<B_ * T_ / 4, 128>>>(aW, aV);
    softmax_ctx_kernel<<<B_, 256>>>();
    dec_kernel<<<NBLK, 256, DEC_SMEM_>>>(x, d_Wih0, d_Whh0, d_b0, d_Wih1, d_Whh1, d_b1);
    pred_kernel<<<B_, 128>>>(qW, qb, (float*)d_out);
}